// round 15
// baseline (speedup 1.0000x reference)
#include <cuda_runtime.h>
#include <cuda_fp16.h>
#include <cstdint>
#include <math.h>

// Problem constants (fixed shapes from reference)
#define BSZ 16384   // batch
#define FF  2048    // n_features
#define HH  4096    // n_hidden
#define DD  4096    // num_of_demos
#define KK  2048    // num_of_features (loss K)

// Scratch (no cudaMalloc allowed). fp16 data stored via casts.
static __device__ float g_buf0[(size_t)BSZ * HH / 2];   // fp16 activations
static __device__ float g_buf1[(size_t)BSZ * HH / 2];   // fp16 activations
static __device__ float g_xr  [(size_t)BSZ * FF / 2];   // fp16 x
static __device__ float g_w1t [(size_t)FF  * HH / 2];   // fp16 [N=HH][K=FF]
static __device__ float g_w2t [(size_t)HH  * HH / 2];   // fp16 [N][K]
static __device__ float g_w3t [(size_t)HH  * HH / 2];   // fp16 [N][K]
static __device__ float g_logits[(size_t)BSZ * 2];      // fused layer4 accum

// ---------------------------------------------------------------------------
// helpers
// ---------------------------------------------------------------------------
__device__ __forceinline__ uint32_t smem_u32(const void* p) {
    uint32_t a;
    asm("{ .reg .u64 t; cvta.to.shared.u64 t, %1; cvt.u32.u64 %0, t; }" : "=r"(a) : "l"(p));
    return a;
}
__device__ __forceinline__ void cp_async16(uint32_t dst, const void* src) {
    asm volatile("cp.async.cg.shared.global [%0], [%1], 16;" :: "r"(dst), "l"(src) : "memory");
}
__device__ __forceinline__ void ldsm4(uint32_t r[4], uint32_t addr) {
    asm volatile("ldmatrix.sync.aligned.m8n8.x4.shared.b16 {%0,%1,%2,%3}, [%4];"
                 : "=r"(r[0]), "=r"(r[1]), "=r"(r[2]), "=r"(r[3]) : "r"(addr));
}
__device__ __forceinline__ void mma16(float c[4], const uint32_t a[4], const uint32_t b[2]) {
    asm volatile(
        "mma.sync.aligned.m16n8k16.row.col.f32.f16.f16.f32 "
        "{%0,%1,%2,%3}, {%4,%5,%6,%7}, {%8,%9}, {%0,%1,%2,%3};\n"
        : "+f"(c[0]), "+f"(c[1]), "+f"(c[2]), "+f"(c[3])
        : "r"(a[0]), "r"(a[1]), "r"(a[2]), "r"(a[3]), "r"(b[0]), "r"(b[1]));
}

__device__ __forceinline__ float block_sum(float v) {
    #pragma unroll
    for (int o = 16; o; o >>= 1) v += __shfl_xor_sync(0xffffffffu, v, o);
    __shared__ float sh[32];
    const int w = threadIdx.x >> 5;
    if ((threadIdx.x & 31) == 0) sh[w] = v;
    __syncthreads();
    const int nw = (blockDim.x + 31) >> 5;
    v = (threadIdx.x < (unsigned)nw) ? sh[threadIdx.x] : 0.f;
    if (threadIdx.x < 32) {
        #pragma unroll
        for (int o = 16; o; o >>= 1) v += __shfl_xor_sync(0xffffffffu, v, o);
    }
    __syncthreads();
    return v;
}

// ---------------------------------------------------------------------------
// prep (ONE launch): z=0..2 -> transpose W1..W3 to [N][K] fp16; z=3 -> x fp16
// ---------------------------------------------------------------------------
__global__ void prep_all_kernel(const float* __restrict__ x,  __half* __restrict__ xr,
                                const float* __restrict__ W1, __half* __restrict__ T1,
                                const float* __restrict__ W2, __half* __restrict__ T2,
                                const float* __restrict__ W3, __half* __restrict__ T3) {
    const int z = blockIdx.z;
    const int tx = threadIdx.x, ty = threadIdx.y;
    if (z == 3) {                      // x conversion: 16384 blocks * 512 float4
        const int blk = blockIdx.y * gridDim.x + blockIdx.x;
        const int tid = ty * 32 + tx;
        #pragma unroll
        for (int h = 0; h < 2; ++h) {
            const int i = blk * 512 + h * 256 + tid;   // < BSZ*FF/4 exactly
            float4 v = ((const float4*)x)[i];
            ((__half2*)xr)[2 * i]     = __floats2half2_rn(v.x, v.y);
            ((__half2*)xr)[2 * i + 1] = __floats2half2_rn(v.z, v.w);
        }
        return;
    }
    const float* W; __half* WT; int K;
    if (z == 0)      { W = W1; WT = T1; K = FF; }
    else if (z == 1) { W = W2; WT = T2; K = HH; }
    else             { W = W3; WT = T3; K = HH; }
    const int n0 = blockIdx.x * 32, k0 = blockIdx.y * 32;
    if (k0 >= K) return;
    __shared__ float t[32][33];
    #pragma unroll
    for (int r = 0; r < 4; ++r)
        t[ty + r * 8][tx] = W[(size_t)(k0 + ty + r * 8) * HH + n0 + tx];
    __syncthreads();
    #pragma unroll
    for (int r = 0; r < 4; ++r)
        WT[(size_t)(n0 + ty + r * 8) * K + k0 + tx] = __float2half_rn(t[tx][ty + r * 8]);
}

// ---------------------------------------------------------------------------
// Loss: single pass. Per-block deterministic sum + one atomicAdd per block.
// ---------------------------------------------------------------------------
__global__ void loss_kernel(const float* __restrict__ dm,
                            const float* __restrict__ alpha,
                            const float* __restrict__ sl,
                            const float* __restrict__ cptr,
                            float* __restrict__ lossp) {
    const int j = blockIdx.x;
    const size_t base = (size_t)j * KK;
    const float c = cptr[0];
    float s = 0.f;
    for (int k = threadIdx.x; k < KK; k += blockDim.x) {
        float m = fmaf(alpha[k], sl[base + k] - dm[base + k], 1.0f);
        s += fmaxf(m, 0.f) - c;
    }
    float tot = block_sum(s);
    if (threadIdx.x == 0) atomicAdd(lossp, tot);
}

// ---------------------------------------------------------------------------
// GEMM core (fp16 in, fp32 accum): R13 mainloop + hoisted stage-issue.
// Block 128x128x64, 4 warps (2Mx2N), warp tile 64x64, m16n8k16.
// 3-stage cp.async + cross-tile register double-buffered ldmatrix fragments.
// Stage issue for tile kt+2 happens inside tile kt (after ks0 MMAs), into
// slot (kt-1)%3 whose readers finished before tile kt began. Boundary is
// sync -> wait_group 0 -> sync (drain g_{kt+2}, issued ~1.6k cyc earlier;
// publishes stages <= kt+2 as required by tile kt+1's reads).
// FUSE_L4=1: epilogue dots relu(acc+bias) with W4 into per-row logits.
// ---------------------------------------------------------------------------
#define BM 128
#define BN 128
#define BK 64
#define ASTG 16384
#define BSTG 16384
#define STG_STRIDE (ASTG + BSTG)
#define NSTAGE 3
#define SMEM_DYN (NSTAGE * STG_STRIDE)

template <int FUSE_L4>
__global__ __launch_bounds__(128, 2)
void gemm_f16(const __half* __restrict__ A, const __half* __restrict__ Wt,
              const float* __restrict__ bias, __half* __restrict__ C,
              const float* __restrict__ w4, float* __restrict__ logits,
              int lda, int ldb, int N, int ktiles) {
    extern __shared__ char dsm[];
    const uint32_t smb = smem_u32(dsm);

    const int tid = threadIdx.x, lane = tid & 31, wid = tid >> 5;
    const int wm = wid & 1, wn = wid >> 1;
    const int gID = lane >> 2, tig = lane & 3;
    const int lj = lane >> 3, li = lane & 7;
    const int bm = blockIdx.y, bn = blockIdx.x;

    const __half* Abase = A  + (size_t)bm * BM * lda;
    const __half* Bbase = Wt + (size_t)bn * BN * ldb;

    const int rowA = wm * 64 + (lj & 1) * 8 + li;
    const int dchA = lj >> 1;
    const int rowB = wn * 64 + (lj >> 1) * 8 + li;
    const int dchB = lj & 1;

    auto issue_stage = [&](int kt, int s) {
        const __half* Ag = Abase + (size_t)kt * BK;
        const __half* Bg = Bbase + (size_t)kt * BK;
        const uint32_t sa = smb + s * STG_STRIDE;
        const uint32_t sb = sa + ASTG;
        #pragma unroll
        for (int i = 0; i < 8; ++i) {
            const int ci = tid + 128 * i;
            const int r = ci >> 3, cc = ci & 7;
            cp_async16(sa + r * 128 + ((cc ^ (r & 7)) << 4),
                       Ag + (size_t)r * lda + cc * 8);
        }
        #pragma unroll
        for (int i = 0; i < 8; ++i) {
            const int ci = tid + 128 * i;
            const int r = ci >> 3, cc = ci & 7;
            cp_async16(sb + r * 128 + ((cc ^ (r & 7)) << 4),
                       Bg + (size_t)r * ldb + cc * 8);
        }
        asm volatile("cp.async.commit_group;" ::: "memory");
    };

    // prologue: stages 0,1 filled and published
    issue_stage(0, 0);
    issue_stage(1, 1);
    asm volatile("cp.async.wait_group 0;" ::: "memory");
    __syncthreads();

    float acc[4][8][4];
    #pragma unroll
    for (int mt = 0; mt < 4; ++mt)
        #pragma unroll
        for (int nt = 0; nt < 8; ++nt)
            #pragma unroll
            for (int r = 0; r < 4; ++r) acc[mt][nt][r] = 0.f;

    uint32_t afr[2][4][4], bfr[2][4][4];
    {
        const uint32_t sa = smb, sb = smb + ASTG;
        #pragma unroll
        for (int mt = 0; mt < 4; ++mt)
            ldsm4(afr[0][mt], sa + (rowA + mt * 16) * 128 + ((dchA ^ li) << 4));
        #pragma unroll
        for (int ntp = 0; ntp < 4; ++ntp)
            ldsm4(bfr[0][ntp], sb + (rowB + ntp * 16) * 128 + ((dchB ^ li) << 4));
    }

    #pragma unroll 1
    for (int kt = 0; kt < ktiles; ++kt) {
        const uint32_t sa = smb + (kt % NSTAGE) * STG_STRIDE;
        const uint32_t sb = sa + ASTG;
        const uint32_t na = smb + ((kt + 1) % NSTAGE) * STG_STRIDE;
        const uint32_t nb = na + ASTG;

        #pragma unroll
        for (int ks = 0; ks < 4; ++ks) {
            const int cur = ks & 1, nxt = cur ^ 1;
            if (ks < 3) {
                const int cb = 2 * (ks + 1);
                #pragma unroll
                for (int mt = 0; mt < 4; ++mt)
                    ldsm4(afr[nxt][mt],
                          sa + (rowA + mt * 16) * 128 + (((cb + dchA) ^ li) << 4));
                #pragma unroll
                for (int ntp = 0; ntp < 4; ++ntp)
                    ldsm4(bfr[nxt][ntp],
                          sb + (rowB + ntp * 16) * 128 + (((cb + dchB) ^ li) << 4));
            } else if (kt + 1 < ktiles) {
                #pragma unroll
                for (int mt = 0; mt < 4; ++mt)
                    ldsm4(afr[nxt][mt],
                          na + (rowA + mt * 16) * 128 + ((dchA ^ li) << 4));
                #pragma unroll
                for (int ntp = 0; ntp < 4; ++ntp)
                    ldsm4(bfr[nxt][ntp],
                          nb + (rowB + ntp * 16) * 128 + ((dchB ^ li) << 4));
            }
            #pragma unroll
            for (int mt = 0; mt < 4; ++mt)
                #pragma unroll
                for (int ntp = 0; ntp < 4; ++ntp) {
                    mma16(acc[mt][2 * ntp],     afr[cur][mt], &bfr[cur][ntp][0]);
                    mma16(acc[mt][2 * ntp + 1], afr[cur][mt], &bfr[cur][ntp][2]);
                }
            // hoisted stage issue: tile kt+2 into slot (kt-1)%3 (readers done)
            if (ks == 0 && kt + 2 < ktiles)
                issue_stage(kt + 2, (kt + 2) % NSTAGE);
        }

        // boundary: drain g_{kt+2}, publish stages <= kt+2
        if (kt + 1 < ktiles) {
            __syncthreads();
            asm volatile("cp.async.wait_group 0;" ::: "memory");
            __syncthreads();
        }
    }

    if (FUSE_L4 == 0) {
        #pragma unroll
        for (int mt = 0; mt < 4; ++mt) {
            const int m0 = bm * BM + wm * 64 + mt * 16 + gID;
            #pragma unroll
            for (int nt = 0; nt < 8; ++nt) {
                const int n = bn * BN + wn * 64 + nt * 8 + tig * 2;
                const float bx = bias[n], by = bias[n + 1];
                __half2 v0 = __floats2half2_rn(fmaxf(acc[mt][nt][0] + bx, 0.f),
                                               fmaxf(acc[mt][nt][1] + by, 0.f));
                __half2 v1 = __floats2half2_rn(fmaxf(acc[mt][nt][2] + bx, 0.f),
                                               fmaxf(acc[mt][nt][3] + by, 0.f));
                *(__half2*)&C[(size_t)m0 * N + n]       = v0;
                *(__half2*)&C[(size_t)(m0 + 8) * N + n] = v1;
            }
        }
    } else {
        // fused layer4: logits[m][c] += sum_n relu(acc+bias)[m][n] * W4[n][c]
        __shared__ float lsm[BM][2];
        if (tid < 64) { lsm[2 * tid][0] = 0.f; lsm[2 * tid][1] = 0.f;
                        lsm[2 * tid + 1][0] = 0.f; lsm[2 * tid + 1][1] = 0.f; }
        __syncthreads();
        #pragma unroll
        for (int mt = 0; mt < 4; ++mt) {
            const int r0 = wm * 64 + mt * 16 + gID;
            float p00 = 0.f, p01 = 0.f, p10 = 0.f, p11 = 0.f;
            #pragma unroll
            for (int nt = 0; nt < 8; ++nt) {
                const int n = bn * BN + wn * 64 + nt * 8 + tig * 2;
                const float bx = bias[n], by = bias[n + 1];
                const float4 w = *(const float4*)(w4 + 2 * n);
                const float h00 = fmaxf(acc[mt][nt][0] + bx, 0.f);
                const float h01 = fmaxf(acc[mt][nt][1] + by, 0.f);
                const float h10 = fmaxf(acc[mt][nt][2] + bx, 0.f);
                const float h11 = fmaxf(acc[mt][nt][3] + by, 0.f);
                p00 = fmaf(h00, w.x, p00); p00 = fmaf(h01, w.z, p00);
                p01 = fmaf(h00, w.y, p01); p01 = fmaf(h01, w.w, p01);
                p10 = fmaf(h10, w.x, p10); p10 = fmaf(h11, w.z, p10);
                p11 = fmaf(h10, w.y, p11); p11 = fmaf(h11, w.w, p11);
            }
            #pragma unroll
            for (int o = 1; o < 4; o <<= 1) {
                p00 += __shfl_xor_sync(0xffffffffu, p00, o);
                p01 += __shfl_xor_sync(0xffffffffu, p01, o);
                p10 += __shfl_xor_sync(0xffffffffu, p10, o);
                p11 += __shfl_xor_sync(0xffffffffu, p11, o);
            }
            if (tig == 0) {
                atomicAdd(&lsm[r0][0], p00);
                atomicAdd(&lsm[r0][1], p01);
                atomicAdd(&lsm[r0 + 8][0], p10);
                atomicAdd(&lsm[r0 + 8][1], p11);
            }
        }
        __syncthreads();
        if (tid < BM) {
            const int m = bm * BM + tid;
            atomicAdd(&logits[2 * m],     lsm[tid][0]);
            atomicAdd(&logits[2 * m + 1], lsm[tid][1]);
        }
    }
}

// ---------------------------------------------------------------------------
// sigmoid over fused logits: probs = sigmoid(logits + b4)
// ---------------------------------------------------------------------------
__global__ void sigmoid_kernel(const float* __restrict__ logits,
                               const float* __restrict__ b4,
                               float* __restrict__ probs) {
    const int i = blockIdx.x * blockDim.x + threadIdx.x;
    if (i < BSZ) {
        const float t0 = logits[2 * i]     + b4[0];
        const float t1 = logits[2 * i + 1] + b4[1];
        probs[2 * i]     = 1.f / (1.f + expf(-t0));
        probs[2 * i + 1] = 1.f / (1.f + expf(-t1));
    }
}

// ---------------------------------------------------------------------------
// Launch
// ---------------------------------------------------------------------------
extern "C" void kernel_launch(void* const* d_in, const int* in_sizes, int n_in,
                              void* d_out, int out_size) {
    const int s = (n_in >= 15) ? 0 : -2;
    const float* x     = (const float*)d_in[0];
    const float* dm    = (const float*)d_in[1];
    const float* alpha = (const float*)d_in[2];
    const float* sl    = (const float*)d_in[3];
    const float* cst   = (const float*)d_in[4];
    const float* W1 = (const float*)d_in[7 + s];
    const float* b1 = (const float*)d_in[8 + s];
    const float* W2 = (const float*)d_in[9 + s];
    const float* b2 = (const float*)d_in[10 + s];
    const float* W3 = (const float*)d_in[11 + s];
    const float* b3 = (const float*)d_in[12 + s];
    const float* W4 = (const float*)d_in[13 + s];
    const float* b4 = (const float*)d_in[14 + s];

    float* out = (float*)d_out;
    float* probs = out + (out_size - 2 * BSZ);
    float* lossp = (out_size > 2 * BSZ) ? out : nullptr;

    void *p0, *p1, *pxr, *pw1, *pw2, *pw3, *plg;
    cudaGetSymbolAddress(&p0,  g_buf0);
    cudaGetSymbolAddress(&p1,  g_buf1);
    cudaGetSymbolAddress(&pxr, g_xr);
    cudaGetSymbolAddress(&pw1, g_w1t);
    cudaGetSymbolAddress(&pw2, g_w2t);
    cudaGetSymbolAddress(&pw3, g_w3t);
    cudaGetSymbolAddress(&plg, g_logits);
    __half* buf0 = (__half*)p0;
    __half* buf1 = (__half*)p1;
    __half* xr   = (__half*)pxr;
    __half* w1t  = (__half*)pw1;
    __half* w2t  = (__half*)pw2;
    __half* w3t  = (__half*)pw3;
    float* logits = (float*)plg;

    // prep (one launch): weights -> [N][K] fp16, x -> fp16
    prep_all_kernel<<<dim3(HH / 32, HH / 32, 4), dim3(32, 8)>>>(
        x, xr, W1, w1t, W2, w2t, W3, w3t);

    // zero accumulators (graph-capturable async memsets)
    cudaMemsetAsync(logits, 0, (size_t)BSZ * 2 * sizeof(float));
    if (lossp) cudaMemsetAsync(lossp, 0, sizeof(float));

    // loss (single pass; per-block deterministic sums + atomic accumulate)
    if (lossp) loss_kernel<<<DD, 256>>>(dm, alpha, sl, cst, lossp);

    cudaFuncSetAttribute(gemm_f16<0>, cudaFuncAttributeMaxDynamicSharedMemorySize, SMEM_DYN);
    cudaFuncSetAttribute(gemm_f16<1>, cudaFuncAttributeMaxDynamicSharedMemorySize, SMEM_DYN);

    dim3 grid(HH / BN, BSZ / BM);  // (32, 128)
    gemm_f16<0><<<grid, 128, SMEM_DYN>>>(xr,   w1t, b1, buf0, nullptr, nullptr,
                                         FF, FF, HH, FF / BK);
    gemm_f16<0><<<grid, 128, SMEM_DYN>>>(buf0, w2t, b2, buf1, nullptr, nullptr,
                                         HH, HH, HH, HH / BK);
    gemm_f16<1><<<grid, 128, SMEM_DYN>>>(buf1, w3t, b3, nullptr, W4, logits,
                                         HH, HH, HH, HH / BK);

    sigmoid_kernel<<<(BSZ + 255) / 256, 256>>>(logits, b4, probs);
}